// round 1
// baseline (speedup 1.0000x reference)
#include <cuda_runtime.h>

#define TN 8192
#define RMAXF 24.0f

// Precomputed radial table: g[i][t][m] = silu(rb(r_i) @ w1[t]) @ w2[t] * (1/sqrt(20))
// Stored as float4 chunks: 12 float4 per entry (3 t * 4 chunks of 4).
__device__ float4 g_table[TN * 12];

__global__ void build_table_kernel(const float* __restrict__ w1,
                                   const float* __restrict__ w2)
{
    int i = blockIdx.x * blockDim.x + threadIdx.x;
    if (i >= TN) return;
    float r = (float)i * (RMAXF / (float)(TN - 1));
    const float step = 4.0f / 9.0f;
    float rb[10];
#pragma unroll
    for (int k = 0; k < 10; k++) {
        float d = (r - (float)k * step) / step;
        rb[k] = expf(-d * d) * 1.12f;
    }
    const float scale = 0.22360679774997896f;  // 1/sqrt(20)
#pragma unroll
    for (int t = 0; t < 3; t++) {
        float h[16];
#pragma unroll
        for (int m = 0; m < 16; m++) h[m] = 0.f;
        const float* W1 = w1 + t * 1000;   // [10][100]
        const float* W2 = w2 + t * 1600;   // [100][16]
        for (int j = 0; j < 100; j++) {
            float a = 0.f;
#pragma unroll
            for (int k = 0; k < 10; k++)
                a = fmaf(rb[k], __ldg(&W1[k * 100 + j]), a);
            float s = a / (1.f + expf(-a));  // silu
#pragma unroll
            for (int m = 0; m < 16; m++)
                h[m] = fmaf(s, __ldg(&W2[j * 16 + m]), h[m]);
        }
#pragma unroll
        for (int q = 0; q < 4; q++) {
            g_table[i * 12 + t * 4 + q] =
                make_float4(h[q * 4 + 0] * scale, h[q * 4 + 1] * scale,
                            h[q * 4 + 2] * scale, h[q * 4 + 3] * scale);
        }
    }
}

__device__ __forceinline__ float dot4(float4 a, float4 b) {
    return fmaf(a.x, b.x, fmaf(a.y, b.y, fmaf(a.z, b.z, a.w * b.w)));
}

__global__ void __launch_bounds__(256) edge_kernel(
    const float* __restrict__ atom_xyz,
    const float* __restrict__ probe_xyz,
    const int*   __restrict__ edges,
    const float* __restrict__ ped,
    const float* __restrict__ cell,
    const float* __restrict__ atom_rep,
    float* __restrict__ probes,
    int E, int n_edges_b, int n_atoms, int n_probes, int AB)
{
    __shared__ float4 s_info[256];
    __shared__ int s_dst[256];
    int tid = threadIdx.x;
    int e = blockIdx.x * 256 + tid;

    // -------- Phase 1: thread = edge; geometry + SH + table dot --------
    if (e < E) {
        int b = e / n_edges_b;
        int2 se = ((const int2*)edges)[e];
        int src_g = b * n_atoms + se.x;
        int dst_g = b * n_probes + se.y;
        float px = ped[3 * e], py = ped[3 * e + 1], pz = ped[3 * e + 2];
        const float* C = cell + b * 9;
        // disp_d = sum_c ped_c * cell[c][d]
        float dx = fmaf(px, __ldg(C + 0), fmaf(py, __ldg(C + 3), pz * __ldg(C + 6)));
        float dy = fmaf(px, __ldg(C + 1), fmaf(py, __ldg(C + 4), pz * __ldg(C + 7)));
        float dz = fmaf(px, __ldg(C + 2), fmaf(py, __ldg(C + 5), pz * __ldg(C + 8)));
        float vx = probe_xyz[3 * dst_g + 0] - atom_xyz[3 * src_g + 0] - dx;
        float vy = probe_xyz[3 * dst_g + 1] - atom_xyz[3 * src_g + 1] - dy;
        float vz = probe_xyz[3 * dst_g + 2] - atom_xyz[3 * src_g + 2] - dz;
        float r2 = fmaf(vx, vx, fmaf(vy, vy, vz * vz));
        float r = sqrtf(r2);
        float rinv = 1.0f / fmaxf(r, 1e-9f);
        float x = vx * rinv, y = vy * rinv, z = vz * rinv;
        float x2 = x * x, y2 = y * y, z2 = z * z;

        const float s3  = 1.7320508075688772f;
        const float s15 = 3.872983346207417f;
        float4 sh0 = make_float4(1.f, s3 * x, s3 * y, s3 * z);
        float4 sh1 = make_float4(s15 * x * y, s15 * y * z,
                                 1.118033988749895f * (3.f * z2 - 1.f),
                                 s15 * x * z);
        float4 sh2 = make_float4(1.9364916731037085f * (x2 - y2),
                                 2.091650066335189f * y * (3.f * x2 - y2),
                                 10.246950765959598f * x * y * z,
                                 1.6201851746019651f * y * (5.f * z2 - 1.f));
        float4 sh3 = make_float4(1.3228756555322954f * (5.f * z2 * z - 3.f * z),
                                 1.6201851746019651f * x * (5.f * z2 - 1.f),
                                 5.123475382979799f * z * (x2 - y2),
                                 2.091650066335189f * x * (x2 - 3.f * y2));

        float f = r * ((float)(TN - 1) / RMAXF);
        f = fminf(f, (float)(TN - 1));
        int i0 = (int)f;
        i0 = min(i0, TN - 2);
        float w = f - (float)i0;

        const float4* G = g_table + i0 * 12;
        float sc[3];
#pragma unroll
        for (int t = 0; t < 3; t++) {
            float d0 = dot4(G[t * 4 + 0], sh0) + dot4(G[t * 4 + 1], sh1) +
                       dot4(G[t * 4 + 2], sh2) + dot4(G[t * 4 + 3], sh3);
            float d1 = dot4(G[12 + t * 4 + 0], sh0) + dot4(G[12 + t * 4 + 1], sh1) +
                       dot4(G[12 + t * 4 + 2], sh2) + dot4(G[12 + t * 4 + 3], sh3);
            sc[t] = fmaf(w, d1 - d0, d0);
        }
        s_info[tid] = make_float4(sc[0], sc[1], sc[2], __int_as_float(src_g));
        s_dst[tid] = dst_g;
    } else {
        s_info[tid] = make_float4(0.f, 0.f, 0.f, 0.f);
        s_dst[tid] = -1;
    }
    __syncthreads();

    // -------- Phase 2: warp = edge; coalesced gather + atomic scatter ----
    int lane = tid & 31;
    int base = (tid >> 5) * 32;
    const float4* rep4 = (const float4*)atom_rep;  // [t][AB][32 float4]
    size_t repT = (size_t)AB * 32;
#pragma unroll 4
    for (int k = 0; k < 32; k++) {
        int dst = s_dst[base + k];
        if (dst < 0) continue;  // warp-uniform (only in last block)
        float4 info = s_info[base + k];
        int src = __float_as_int(info.w);
        const float4* p0 = rep4 + (size_t)src * 32 + lane;
        float4 a0 = __ldg(p0);
        float4 a1 = __ldg(p0 + repT);
        float4 a2 = __ldg(p0 + 2 * repT);
        float4 m;
        m.x = fmaf(info.x, a0.x, fmaf(info.y, a1.x, info.z * a2.x));
        m.y = fmaf(info.x, a0.y, fmaf(info.y, a1.y, info.z * a2.y));
        m.z = fmaf(info.x, a0.z, fmaf(info.y, a1.z, info.z * a2.z));
        m.w = fmaf(info.x, a0.w, fmaf(info.y, a1.w, info.z * a2.w));
        float* dptr = probes + (size_t)dst * 128 + lane * 4;
        atomicAdd(dptr + 0, m.x);
        atomicAdd(dptr + 1, m.y);
        atomicAdd(dptr + 2, m.z);
        atomicAdd(dptr + 3, m.w);
    }
}

__global__ void out_kernel(const float* __restrict__ probes,
                           const float* __restrict__ w_out,
                           float* __restrict__ out, int P)
{
    int g = blockIdx.x * blockDim.x + threadIdx.x;
    int p = g >> 5;
    int lane = g & 31;
    if (p >= P) return;
    float4 a = __ldg((const float4*)probes + (size_t)p * 32 + lane);
    float4 wv = __ldg((const float4*)w_out + lane);
    float s = fmaf(a.x, wv.x, fmaf(a.y, wv.y, fmaf(a.z, wv.z, a.w * wv.w)));
#pragma unroll
    for (int off = 16; off > 0; off >>= 1)
        s += __shfl_xor_sync(0xFFFFFFFFu, s, off);
    if (lane == 0) out[p] = s;
}

extern "C" void kernel_launch(void* const* d_in, const int* in_sizes, int n_in,
                              void* d_out, int out_size)
{
    const float* atom_xyz  = (const float*)d_in[0];
    const float* probe_xyz = (const float*)d_in[1];
    const int*   edges     = (const int*)d_in[2];
    const float* ped       = (const float*)d_in[3];
    const float* cell      = (const float*)d_in[4];
    const float* atom_rep  = (const float*)d_in[8];
    const float* w1        = (const float*)d_in[9];
    const float* w2        = (const float*)d_in[10];
    const float* w_out     = (const float*)d_in[11];

    int B         = in_sizes[4] / 9;
    int n_atoms   = in_sizes[0] / (3 * B);
    int n_probes  = in_sizes[1] / (3 * B);
    int n_edges_b = in_sizes[2] / (2 * B);
    int E  = B * n_edges_b;
    int AB = B * n_atoms;
    int P  = B * n_probes;

    float* out    = (float*)d_out;      // first P elements: (B,P) potential
    float* probes = out + P;            // next P*128: probe features

    cudaMemsetAsync(probes, 0, (size_t)P * 128 * sizeof(float), 0);
    build_table_kernel<<<(TN + 127) / 128, 128>>>(w1, w2);
    edge_kernel<<<(E + 255) / 256, 256>>>(atom_xyz, probe_xyz, edges, ped, cell,
                                          atom_rep, probes,
                                          E, n_edges_b, n_atoms, n_probes, AB);
    out_kernel<<<(P * 32 + 255) / 256, 256>>>(probes, w_out, out, P);
}

// round 2
// speedup vs baseline: 1.4954x; 1.4954x over previous
#include <cuda_runtime.h>

#define TN 4096
#define RMAXF 8.0f

// Precomputed radial table: g[i][t][m] = silu(rb(r_i) @ w1[t]) @ w2[t] * (1/sqrt(20))
// Stored as float4 chunks: 12 float4 per entry (3 t * 4 chunks of 4).
// g(r) == 0 exactly for r >~ 6.5 (gaussians vanish, silu(0)=0), so clamping
// r>RMAXF to the last entries is exact.
__device__ float4 g_table[TN * 12];

// Warp-per-entry: lanes split the 100 hidden units, shfl-reduce 16 outputs.
__global__ void __launch_bounds__(256) build_table_kernel(
    const float* __restrict__ w1, const float* __restrict__ w2)
{
    int warp = (blockIdx.x * blockDim.x + threadIdx.x) >> 5;
    int lane = threadIdx.x & 31;
    if (warp >= TN) return;
    int i = warp;

    float r = (float)i * (RMAXF / (float)(TN - 1));
    const float step = 4.0f / 9.0f;
    float rb[10];
#pragma unroll
    for (int k = 0; k < 10; k++) {
        float d = (r - (float)k * step) / step;
        rb[k] = expf(-d * d) * 1.12f;
    }
    const float scale = 0.22360679774997896f;  // 1/sqrt(20)

#pragma unroll
    for (int t = 0; t < 3; t++) {
        const float* W1 = w1 + t * 1000;   // [10][100]
        const float* W2 = w2 + t * 1600;   // [100][16]
        float h[16];
#pragma unroll
        for (int m = 0; m < 16; m++) h[m] = 0.f;

        // lanes 0..31 take j = lane, lane+32, lane+64; lanes 0..3 also j=96..99
        for (int j = lane; j < 100; j += 32) {
            float a = 0.f;
#pragma unroll
            for (int k = 0; k < 10; k++)
                a = fmaf(rb[k], __ldg(&W1[k * 100 + j]), a);
            float s = a / (1.f + expf(-a));  // silu
#pragma unroll
            for (int m = 0; m < 16; m++)
                h[m] = fmaf(s, __ldg(&W2[j * 16 + m]), h[m]);
        }

        // warp reduction of the 16 partials
#pragma unroll
        for (int m = 0; m < 16; m++) {
#pragma unroll
            for (int off = 16; off > 0; off >>= 1)
                h[m] += __shfl_xor_sync(0xFFFFFFFFu, h[m], off);
        }

        if (lane < 4) {
            g_table[i * 12 + t * 4 + lane] =
                make_float4(h[lane * 4 + 0] * scale, h[lane * 4 + 1] * scale,
                            h[lane * 4 + 2] * scale, h[lane * 4 + 3] * scale);
        }
    }
}

__device__ __forceinline__ float dot4(float4 a, float4 b) {
    return fmaf(a.x, b.x, fmaf(a.y, b.y, fmaf(a.z, b.z, a.w * b.w)));
}

__global__ void __launch_bounds__(256) edge_kernel(
    const float* __restrict__ atom_xyz,
    const float* __restrict__ probe_xyz,
    const int*   __restrict__ edges,
    const float* __restrict__ ped,
    const float* __restrict__ cell,
    const float* __restrict__ atom_rep,
    float* __restrict__ probes,
    int E, int n_edges_b, int n_atoms, int n_probes, int AB)
{
    __shared__ float4 s_info[256];
    __shared__ int s_dst[256];
    int tid = threadIdx.x;
    int e = blockIdx.x * 256 + tid;

    // -------- Phase 1: thread = edge; geometry + SH + table dot --------
    if (e < E) {
        int b = e / n_edges_b;
        int2 se = ((const int2*)edges)[e];
        int src_g = b * n_atoms + se.x;
        int dst_g = b * n_probes + se.y;
        float px = ped[3 * e], py = ped[3 * e + 1], pz = ped[3 * e + 2];
        const float* C = cell + b * 9;
        // disp_d = sum_c ped_c * cell[c][d]
        float dx = fmaf(px, __ldg(C + 0), fmaf(py, __ldg(C + 3), pz * __ldg(C + 6)));
        float dy = fmaf(px, __ldg(C + 1), fmaf(py, __ldg(C + 4), pz * __ldg(C + 7)));
        float dz = fmaf(px, __ldg(C + 2), fmaf(py, __ldg(C + 5), pz * __ldg(C + 8)));
        float vx = probe_xyz[3 * dst_g + 0] - atom_xyz[3 * src_g + 0] - dx;
        float vy = probe_xyz[3 * dst_g + 1] - atom_xyz[3 * src_g + 1] - dy;
        float vz = probe_xyz[3 * dst_g + 2] - atom_xyz[3 * src_g + 2] - dz;
        float r2 = fmaf(vx, vx, fmaf(vy, vy, vz * vz));
        float r = sqrtf(r2);
        float rinv = 1.0f / fmaxf(r, 1e-9f);
        float x = vx * rinv, y = vy * rinv, z = vz * rinv;
        float x2 = x * x, y2 = y * y, z2 = z * z;

        const float s3  = 1.7320508075688772f;
        const float s15 = 3.872983346207417f;
        float4 sh0 = make_float4(1.f, s3 * x, s3 * y, s3 * z);
        float4 sh1 = make_float4(s15 * x * y, s15 * y * z,
                                 1.118033988749895f * (3.f * z2 - 1.f),
                                 s15 * x * z);
        float4 sh2 = make_float4(1.9364916731037085f * (x2 - y2),
                                 2.091650066335189f * y * (3.f * x2 - y2),
                                 10.246950765959598f * x * y * z,
                                 1.6201851746019651f * y * (5.f * z2 - 1.f));
        float4 sh3 = make_float4(1.3228756555322954f * (5.f * z2 * z - 3.f * z),
                                 1.6201851746019651f * x * (5.f * z2 - 1.f),
                                 5.123475382979799f * z * (x2 - y2),
                                 2.091650066335189f * x * (x2 - 3.f * y2));

        float f = r * ((float)(TN - 1) / RMAXF);
        f = fminf(f, (float)(TN - 1));
        int i0 = (int)f;
        i0 = min(i0, TN - 2);
        float w = f - (float)i0;

        const float4* G = g_table + i0 * 12;
        float sc[3];
#pragma unroll
        for (int t = 0; t < 3; t++) {
            float d0 = dot4(G[t * 4 + 0], sh0) + dot4(G[t * 4 + 1], sh1) +
                       dot4(G[t * 4 + 2], sh2) + dot4(G[t * 4 + 3], sh3);
            float d1 = dot4(G[12 + t * 4 + 0], sh0) + dot4(G[12 + t * 4 + 1], sh1) +
                       dot4(G[12 + t * 4 + 2], sh2) + dot4(G[12 + t * 4 + 3], sh3);
            sc[t] = fmaf(w, d1 - d0, d0);
        }
        s_info[tid] = make_float4(sc[0], sc[1], sc[2], __int_as_float(src_g));
        s_dst[tid] = dst_g;
    } else {
        s_info[tid] = make_float4(0.f, 0.f, 0.f, 0.f);
        s_dst[tid] = -1;
    }
    __syncthreads();

    // -------- Phase 2: warp = edge; coalesced gather + atomic scatter ----
    int lane = tid & 31;
    int base = (tid >> 5) * 32;
    const float4* rep4 = (const float4*)atom_rep;  // [t][AB][32 float4]
    size_t repT = (size_t)AB * 32;
#pragma unroll 4
    for (int k = 0; k < 32; k++) {
        int dst = s_dst[base + k];
        if (dst < 0) continue;  // warp-uniform (only in last block)
        float4 info = s_info[base + k];
        int src = __float_as_int(info.w);
        const float4* p0 = rep4 + (size_t)src * 32 + lane;
        float4 a0 = __ldg(p0);
        float4 a1 = __ldg(p0 + repT);
        float4 a2 = __ldg(p0 + 2 * repT);
        float4 m;
        m.x = fmaf(info.x, a0.x, fmaf(info.y, a1.x, info.z * a2.x));
        m.y = fmaf(info.x, a0.y, fmaf(info.y, a1.y, info.z * a2.y));
        m.z = fmaf(info.x, a0.z, fmaf(info.y, a1.z, info.z * a2.z));
        m.w = fmaf(info.x, a0.w, fmaf(info.y, a1.w, info.z * a2.w));
        float* dptr = probes + (size_t)dst * 128 + lane * 4;
        atomicAdd(dptr + 0, m.x);
        atomicAdd(dptr + 1, m.y);
        atomicAdd(dptr + 2, m.z);
        atomicAdd(dptr + 3, m.w);
    }
}

__global__ void out_kernel(const float* __restrict__ probes,
                           const float* __restrict__ w_out,
                           float* __restrict__ out, int P)
{
    int g = blockIdx.x * blockDim.x + threadIdx.x;
    int p = g >> 5;
    int lane = g & 31;
    if (p >= P) return;
    float4 a = __ldg((const float4*)probes + (size_t)p * 32 + lane);
    float4 wv = __ldg((const float4*)w_out + lane);
    float s = fmaf(a.x, wv.x, fmaf(a.y, wv.y, fmaf(a.z, wv.z, a.w * wv.w)));
#pragma unroll
    for (int off = 16; off > 0; off >>= 1)
        s += __shfl_xor_sync(0xFFFFFFFFu, s, off);
    if (lane == 0) out[p] = s;
}

extern "C" void kernel_launch(void* const* d_in, const int* in_sizes, int n_in,
                              void* d_out, int out_size)
{
    const float* atom_xyz  = (const float*)d_in[0];
    const float* probe_xyz = (const float*)d_in[1];
    const int*   edges     = (const int*)d_in[2];
    const float* ped       = (const float*)d_in[3];
    const float* cell      = (const float*)d_in[4];
    const float* atom_rep  = (const float*)d_in[8];
    const float* w1        = (const float*)d_in[9];
    const float* w2        = (const float*)d_in[10];
    const float* w_out     = (const float*)d_in[11];

    int B         = in_sizes[4] / 9;
    int n_atoms   = in_sizes[0] / (3 * B);
    int n_probes  = in_sizes[1] / (3 * B);
    int n_edges_b = in_sizes[2] / (2 * B);
    int E  = B * n_edges_b;
    int AB = B * n_atoms;
    int P  = B * n_probes;

    float* out    = (float*)d_out;      // first P elements: (B,P) potential
    float* probes = out + P;            // next P*128: probe features

    cudaMemsetAsync(probes, 0, (size_t)P * 128 * sizeof(float), 0);
    // 8 warps/block, warp per table entry
    build_table_kernel<<<(TN * 32 + 255) / 256, 256>>>(w1, w2);
    edge_kernel<<<(E + 255) / 256, 256>>>(atom_xyz, probe_xyz, edges, ped, cell,
                                          atom_rep, probes,
                                          E, n_edges_b, n_atoms, n_probes, AB);
    out_kernel<<<(P * 32 + 255) / 256, 256>>>(probes, w_out, out, P);
}

// round 3
// speedup vs baseline: 2.1873x; 1.4627x over previous
#include <cuda_runtime.h>

#define TN 4096
#define RMAXF 8.0f

// Radial table: g_table[i][t*16+m] = (silu(rb(r_i)@w1[t]) @ w2[t])[m] / sqrt(20)
// 48 floats per entry. g(r)==0 exactly for r >~ 6.5 (gaussians vanish,
// silu(0)=0), so clamping r>RMAXF into the zero tail is exact.
__device__ float g_table[TN * 48];

// Warp-per-entry, two intra-warp passes via smem so all GMEM access is coalesced.
__global__ void __launch_bounds__(256) build_table_kernel(
    const float* __restrict__ w1, const float* __restrict__ w2)
{
    __shared__ float s_s[8][100];
    int wlocal = threadIdx.x >> 5;
    int lane = threadIdx.x & 31;
    int i = blockIdx.x * 8 + wlocal;
    if (i >= TN) return;

    float r = (float)i * (RMAXF / (float)(TN - 1));
    const float step = 4.0f / 9.0f;
    float ev = 0.f;
    if (lane < 10) {
        float d = (r - (float)lane * step) / step;
        ev = expf(-d * d) * 1.12f;
    }
    float rb[10];
#pragma unroll
    for (int k = 0; k < 10; k++) rb[k] = __shfl_sync(0xFFFFFFFFu, ev, k);

    const float scale = 0.22360679774997896f;  // 1/sqrt(20)

#pragma unroll
    for (int t = 0; t < 3; t++) {
        const float* W1 = w1 + t * 1000;   // [10][100]
        const float* W2 = w2 + t * 1600;   // [100][16]
        // pass a: s[j] = silu(rb @ W1[:,j]), lanes split j (coalesced W1)
        for (int j = lane; j < 100; j += 32) {
            float a = 0.f;
#pragma unroll
            for (int k = 0; k < 10; k++)
                a = fmaf(rb[k], __ldg(&W1[k * 100 + j]), a);
            s_s[wlocal][j] = a / (1.f + expf(-a));
        }
        __syncwarp();
        // pass b: lane m owns output m; W2 loads coalesced across lanes
        if (lane < 16) {
            float h = 0.f;
#pragma unroll 4
            for (int j = 0; j < 100; j++)
                h = fmaf(s_s[wlocal][j], __ldg(&W2[j * 16 + lane]), h);
            g_table[i * 48 + t * 16 + lane] = h * scale;
        }
        __syncwarp();
    }
}

__global__ void __launch_bounds__(256) edge_kernel(
    const float* __restrict__ atom_xyz,
    const float* __restrict__ probe_xyz,
    const int*   __restrict__ edges,
    const float* __restrict__ ped,
    const float* __restrict__ cell,
    const float* __restrict__ atom_rep,
    float* __restrict__ probes,
    int E, int n_edges_b, int n_atoms, int n_probes, int AB)
{
    __shared__ float s_sh[256 * 17];   // sh[16] per edge, pitch 17 (bank-safe)
    __shared__ int   s_i0[256];
    __shared__ float s_w[256];
    __shared__ int   s_src[256];
    __shared__ int   s_dst[256];
    __shared__ float s_sc[256 * 4];    // 3 scalars per edge, pitch 4

    int tid = threadIdx.x;
    int e = blockIdx.x * 256 + tid;

    // ---- Phase 1: thread = edge; geometry + SH + table index ----
    if (e < E) {
        int b = e / n_edges_b;
        int2 se = ((const int2*)edges)[e];
        int src_g = b * n_atoms + se.x;
        int dst_g = b * n_probes + se.y;
        float px = ped[3 * e], py = ped[3 * e + 1], pz = ped[3 * e + 2];
        const float* C = cell + b * 9;
        float dx = fmaf(px, __ldg(C + 0), fmaf(py, __ldg(C + 3), pz * __ldg(C + 6)));
        float dy = fmaf(px, __ldg(C + 1), fmaf(py, __ldg(C + 4), pz * __ldg(C + 7)));
        float dz = fmaf(px, __ldg(C + 2), fmaf(py, __ldg(C + 5), pz * __ldg(C + 8)));
        float vx = probe_xyz[3 * dst_g + 0] - atom_xyz[3 * src_g + 0] - dx;
        float vy = probe_xyz[3 * dst_g + 1] - atom_xyz[3 * src_g + 1] - dy;
        float vz = probe_xyz[3 * dst_g + 2] - atom_xyz[3 * src_g + 2] - dz;
        float r2 = fmaf(vx, vx, fmaf(vy, vy, vz * vz));
        float r = sqrtf(r2);
        float rinv = 1.0f / fmaxf(r, 1e-9f);
        float x = vx * rinv, y = vy * rinv, z = vz * rinv;
        float x2 = x * x, y2 = y * y, z2 = z * z;

        const float s3  = 1.7320508075688772f;
        const float s15 = 3.872983346207417f;
        float* S = s_sh + tid * 17;
        S[0]  = 1.f;
        S[1]  = s3 * x;
        S[2]  = s3 * y;
        S[3]  = s3 * z;
        S[4]  = s15 * x * y;
        S[5]  = s15 * y * z;
        S[6]  = 1.118033988749895f * (3.f * z2 - 1.f);
        S[7]  = s15 * x * z;
        S[8]  = 1.9364916731037085f * (x2 - y2);
        S[9]  = 2.091650066335189f * y * (3.f * x2 - y2);
        S[10] = 10.246950765959598f * x * y * z;
        S[11] = 1.6201851746019651f * y * (5.f * z2 - 1.f);
        S[12] = 1.3228756555322954f * (5.f * z2 * z - 3.f * z);
        S[13] = 1.6201851746019651f * x * (5.f * z2 - 1.f);
        S[14] = 5.123475382979799f * z * (x2 - y2);
        S[15] = 2.091650066335189f * x * (x2 - 3.f * y2);

        float f = r * ((float)(TN - 1) / RMAXF);
        f = fminf(f, (float)(TN - 1));
        int i0 = (int)f;
        i0 = min(i0, TN - 2);
        s_i0[tid] = i0;
        s_w[tid] = f - (float)i0;
        s_src[tid] = src_g;
        s_dst[tid] = dst_g;
    } else {
        float* S = s_sh + tid * 17;
#pragma unroll
        for (int m = 0; m < 16; m++) S[m] = 0.f;
        s_i0[tid] = 0;
        s_w[tid] = 0.f;
        s_src[tid] = 0;
        s_dst[tid] = -1;
    }
    __syncthreads();

    // ---- Phase 1.5: half-warp = edge; coalesced table read + reduce ----
    {
        int lane = tid & 31;
        int m = lane & 15;
        int hw = (tid >> 5) * 2 + (lane >> 4);  // half-warp id 0..15
#pragma unroll 2
        for (int k = 0; k < 16; k++) {
            int el = hw * 16 + k;
            int i0 = s_i0[el];
            float w = s_w[el];
            float shm = s_sh[el * 17 + m];
            const float* G = g_table + i0 * 48 + m;
#pragma unroll
            for (int t = 0; t < 3; t++) {
                float g0 = __ldg(G + t * 16);
                float g1 = __ldg(G + 48 + t * 16);
                float v = shm * fmaf(w, g1 - g0, g0);
                v += __shfl_xor_sync(0xFFFFFFFFu, v, 1);
                v += __shfl_xor_sync(0xFFFFFFFFu, v, 2);
                v += __shfl_xor_sync(0xFFFFFFFFu, v, 4);
                v += __shfl_xor_sync(0xFFFFFFFFu, v, 8);
                if (m == 0) s_sc[el * 4 + t] = v;
            }
        }
    }
    __syncthreads();

    // ---- Phase 2: warp = edge; coalesced gather + vector red scatter ----
    int lane = tid & 31;
    int base = (tid >> 5) * 32;
    const float4* rep4 = (const float4*)atom_rep;  // [t][AB][32 float4]
    size_t repT = (size_t)AB * 32;
#pragma unroll 4
    for (int k = 0; k < 32; k++) {
        int el = base + k;
        int dst = s_dst[el];
        if (dst < 0) continue;  // warp-uniform (only in last block)
        float c0 = s_sc[el * 4 + 0];
        float c1 = s_sc[el * 4 + 1];
        float c2 = s_sc[el * 4 + 2];
        int src = s_src[el];
        const float4* p0 = rep4 + (size_t)src * 32 + lane;
        float4 a0 = __ldg(p0);
        float4 a1 = __ldg(p0 + repT);
        float4 a2 = __ldg(p0 + 2 * repT);
        float4 m;
        m.x = fmaf(c0, a0.x, fmaf(c1, a1.x, c2 * a2.x));
        m.y = fmaf(c0, a0.y, fmaf(c1, a1.y, c2 * a2.y));
        m.z = fmaf(c0, a0.z, fmaf(c1, a1.z, c2 * a2.z));
        m.w = fmaf(c0, a0.w, fmaf(c1, a1.w, c2 * a2.w));
        float* dptr = probes + (size_t)dst * 128 + lane * 4;
        asm volatile("red.global.add.v4.f32 [%0], {%1, %2, %3, %4};"
                     :: "l"(dptr), "f"(m.x), "f"(m.y), "f"(m.z), "f"(m.w)
                     : "memory");
    }
}

__global__ void out_kernel(const float* __restrict__ probes,
                           const float* __restrict__ w_out,
                           float* __restrict__ out, int P)
{
    int g = blockIdx.x * blockDim.x + threadIdx.x;
    int p = g >> 5;
    int lane = g & 31;
    if (p >= P) return;
    float4 a = __ldg((const float4*)probes + (size_t)p * 32 + lane);
    float4 wv = __ldg((const float4*)w_out + lane);
    float s = fmaf(a.x, wv.x, fmaf(a.y, wv.y, fmaf(a.z, wv.z, a.w * wv.w)));
#pragma unroll
    for (int off = 16; off > 0; off >>= 1)
        s += __shfl_xor_sync(0xFFFFFFFFu, s, off);
    if (lane == 0) out[p] = s;
}

extern "C" void kernel_launch(void* const* d_in, const int* in_sizes, int n_in,
                              void* d_out, int out_size)
{
    const float* atom_xyz  = (const float*)d_in[0];
    const float* probe_xyz = (const float*)d_in[1];
    const int*   edges     = (const int*)d_in[2];
    const float* ped       = (const float*)d_in[3];
    const float* cell      = (const float*)d_in[4];
    const float* atom_rep  = (const float*)d_in[8];
    const float* w1        = (const float*)d_in[9];
    const float* w2        = (const float*)d_in[10];
    const float* w_out     = (const float*)d_in[11];

    int B         = in_sizes[4] / 9;
    int n_atoms   = in_sizes[0] / (3 * B);
    int n_probes  = in_sizes[1] / (3 * B);
    int n_edges_b = in_sizes[2] / (2 * B);
    int E  = B * n_edges_b;
    int AB = B * n_atoms;
    int P  = B * n_probes;

    float* out    = (float*)d_out;      // first P elements: (B,P) potential
    float* probes = out + P;            // next P*128: probe features

    cudaMemsetAsync(probes, 0, (size_t)P * 128 * sizeof(float), 0);
    build_table_kernel<<<(TN + 7) / 8, 256>>>(w1, w2);
    edge_kernel<<<(E + 255) / 256, 256>>>(atom_xyz, probe_xyz, edges, ped, cell,
                                          atom_rep, probes,
                                          E, n_edges_b, n_atoms, n_probes, AB);
    out_kernel<<<(P * 32 + 255) / 256, 256>>>(probes, w_out, out, P);
}

// round 4
// speedup vs baseline: 2.4086x; 1.1012x over previous
#include <cuda_runtime.h>

#define TN 2048
#define RMAXF 8.0f

// Radial table: g_table[i][t*16+m] = (silu(rb(r_i)@w1[t]) @ w2[t])[m] / sqrt(20)
// 48 floats per entry. g(r)==0 exactly for r >~ 6.5 (gaussians vanish,
// silu(0)=0), so clamping r>RMAXF into the zero tail is exact.
__device__ float g_table[TN * 48];
// rw[t*AB + a] = dot(atom_rep[t][a][:], w_out)   (slack for AB up to 64k)
__device__ float rw_table[3 * 65536];

// Warp-per-entry, two intra-warp passes via smem so all GMEM access is coalesced.
__global__ void __launch_bounds__(256) build_table_kernel(
    const float* __restrict__ w1, const float* __restrict__ w2)
{
    __shared__ float s_s[8][100];
    int wlocal = threadIdx.x >> 5;
    int lane = threadIdx.x & 31;
    int i = blockIdx.x * 8 + wlocal;
    if (i >= TN) return;

    float r = (float)i * (RMAXF / (float)(TN - 1));
    const float step = 4.0f / 9.0f;
    float ev = 0.f;
    if (lane < 10) {
        float d = (r - (float)lane * step) / step;
        ev = expf(-d * d) * 1.12f;
    }
    float rb[10];
#pragma unroll
    for (int k = 0; k < 10; k++) rb[k] = __shfl_sync(0xFFFFFFFFu, ev, k);

    const float scale = 0.22360679774997896f;  // 1/sqrt(20)

    // pass a: s[j] = silu over ALL 3 t stacked would differ; per t we need
    // separate hidden activations, so keep per-t pass a but fuse pass b
    // across all 48 outputs using every lane.
    // s_s reused per t; to use all lanes in pass b for all t at once we
    // store all 300 activations? 8 warps * 300 floats = 9.6KB -> ok.
    __shared__ float s_all[8][3][100];
#pragma unroll
    for (int t = 0; t < 3; t++) {
        const float* W1 = w1 + t * 1000;   // [10][100]
        for (int j = lane; j < 100; j += 32) {
            float a = 0.f;
#pragma unroll
            for (int k = 0; k < 10; k++)
                a = fmaf(rb[k], __ldg(&W1[k * 100 + j]), a);
            s_all[wlocal][t][j] = a / (1.f + expf(-a));
        }
    }
    __syncwarp();
    (void)s_s;

    // pass b: flattened outputs o in [0,48); lane does o=lane and o=lane+32.
    int o1 = lane;            // t = o1>>4, m = o1&15
    int o2 = 32 + lane;       // valid when lane < 16
    int t1 = o1 >> 4, m1 = o1 & 15;
    int t2 = 2,       m2 = lane;  // o2>>4 == 2
    float h1 = 0.f, h2 = 0.f;
    const float* s1 = s_all[wlocal][t1];
    const float* s2 = s_all[wlocal][t2];
#pragma unroll 4
    for (int j = 0; j < 100; j++) {
        h1 = fmaf(s1[j], __ldg(&w2[t1 * 1600 + j * 16 + m1]), h1);
        if (lane < 16)
            h2 = fmaf(s2[j], __ldg(&w2[t2 * 1600 + j * 16 + m2]), h2);
    }
    g_table[i * 48 + o1] = h1 * scale;
    if (lane < 16) g_table[i * 48 + o2] = h2 * scale;
}

// warp per row: rw[row] = dot(atom_rep[row*128 .. +128], w_out)
__global__ void rw_kernel(const float* __restrict__ atom_rep,
                          const float* __restrict__ w_out, int rows)
{
    int g = blockIdx.x * blockDim.x + threadIdx.x;
    int row = g >> 5;
    int lane = g & 31;
    if (row >= rows) return;
    float4 a = __ldg((const float4*)atom_rep + (size_t)row * 32 + lane);
    float4 wv = __ldg((const float4*)w_out + lane);
    float s = fmaf(a.x, wv.x, fmaf(a.y, wv.y, fmaf(a.z, wv.z, a.w * wv.w)));
#pragma unroll
    for (int off = 16; off > 0; off >>= 1)
        s += __shfl_xor_sync(0xFFFFFFFFu, s, off);
    if (lane == 0) rw_table[row] = s;
}

__global__ void __launch_bounds__(256) edge_kernel(
    const float* __restrict__ atom_xyz,
    const float* __restrict__ probe_xyz,
    const int*   __restrict__ edges,
    const float* __restrict__ ped,
    const float* __restrict__ cell,
    const float* __restrict__ atom_rep,
    float* __restrict__ probes,
    float* __restrict__ out,
    int E, int n_edges_b, int n_atoms, int n_probes, int AB)
{
    __shared__ float s_sh[256 * 17];   // sh[16] per edge, pitch 17 (bank-safe)
    __shared__ int   s_i0[256];
    __shared__ float s_w[256];
    __shared__ int   s_src[256];
    __shared__ int   s_dst[256];
    __shared__ float s_sc[256 * 4];    // 3 scalars per edge, pitch 4

    int tid = threadIdx.x;
    int e = blockIdx.x * 256 + tid;

    // ---- Phase 1: thread = edge; geometry + SH + table index ----
    if (e < E) {
        int b = e / n_edges_b;
        int2 se = ((const int2*)edges)[e];
        int src_g = b * n_atoms + se.x;
        int dst_g = b * n_probes + se.y;
        float px = ped[3 * e], py = ped[3 * e + 1], pz = ped[3 * e + 2];
        const float* C = cell + b * 9;
        float dx = fmaf(px, __ldg(C + 0), fmaf(py, __ldg(C + 3), pz * __ldg(C + 6)));
        float dy = fmaf(px, __ldg(C + 1), fmaf(py, __ldg(C + 4), pz * __ldg(C + 7)));
        float dz = fmaf(px, __ldg(C + 2), fmaf(py, __ldg(C + 5), pz * __ldg(C + 8)));
        float vx = probe_xyz[3 * dst_g + 0] - atom_xyz[3 * src_g + 0] - dx;
        float vy = probe_xyz[3 * dst_g + 1] - atom_xyz[3 * src_g + 1] - dy;
        float vz = probe_xyz[3 * dst_g + 2] - atom_xyz[3 * src_g + 2] - dz;
        float r2 = fmaf(vx, vx, fmaf(vy, vy, vz * vz));
        float r = sqrtf(r2);
        float rinv = 1.0f / fmaxf(r, 1e-9f);
        float x = vx * rinv, y = vy * rinv, z = vz * rinv;
        float x2 = x * x, y2 = y * y, z2 = z * z;

        const float s3  = 1.7320508075688772f;
        const float s15 = 3.872983346207417f;
        float* S = s_sh + tid * 17;
        S[0]  = 1.f;
        S[1]  = s3 * x;
        S[2]  = s3 * y;
        S[3]  = s3 * z;
        S[4]  = s15 * x * y;
        S[5]  = s15 * y * z;
        S[6]  = 1.118033988749895f * (3.f * z2 - 1.f);
        S[7]  = s15 * x * z;
        S[8]  = 1.9364916731037085f * (x2 - y2);
        S[9]  = 2.091650066335189f * y * (3.f * x2 - y2);
        S[10] = 10.246950765959598f * x * y * z;
        S[11] = 1.6201851746019651f * y * (5.f * z2 - 1.f);
        S[12] = 1.3228756555322954f * (5.f * z2 * z - 3.f * z);
        S[13] = 1.6201851746019651f * x * (5.f * z2 - 1.f);
        S[14] = 5.123475382979799f * z * (x2 - y2);
        S[15] = 2.091650066335189f * x * (x2 - 3.f * y2);

        float f = r * ((float)(TN - 1) / RMAXF);
        f = fminf(f, (float)(TN - 1));
        int i0 = (int)f;
        i0 = min(i0, TN - 2);
        s_i0[tid] = i0;
        s_w[tid] = f - (float)i0;
        s_src[tid] = src_g;
        s_dst[tid] = dst_g;
    } else {
        float* S = s_sh + tid * 17;
#pragma unroll
        for (int m = 0; m < 16; m++) S[m] = 0.f;
        s_i0[tid] = 0;
        s_w[tid] = 0.f;
        s_src[tid] = 0;
        s_dst[tid] = -1;
    }
    __syncthreads();

    // ---- Phase 1.5: half-warp = edge; coalesced table read + reduce ----
    {
        int lane = tid & 31;
        int m = lane & 15;
        int hw = (tid >> 5) * 2 + (lane >> 4);  // half-warp id 0..15
#pragma unroll 2
        for (int k = 0; k < 16; k++) {
            int el = hw * 16 + k;
            int i0 = s_i0[el];
            float w = s_w[el];
            float shm = s_sh[el * 17 + m];
            const float* G = g_table + i0 * 48 + m;
#pragma unroll
            for (int t = 0; t < 3; t++) {
                float g0 = __ldg(G + t * 16);
                float g1 = __ldg(G + 48 + t * 16);
                float v = shm * fmaf(w, g1 - g0, g0);
                v += __shfl_xor_sync(0xFFFFFFFFu, v, 1);
                v += __shfl_xor_sync(0xFFFFFFFFu, v, 2);
                v += __shfl_xor_sync(0xFFFFFFFFu, v, 4);
                v += __shfl_xor_sync(0xFFFFFFFFu, v, 8);
                if (m == 0) s_sc[el * 4 + t] = v;
            }
        }
    }
    __syncthreads();

    // ---- Phase 2: warp = edge; coalesced gather + vector red scatter ----
    int lane = tid & 31;
    int base = (tid >> 5) * 32;
    const float4* rep4 = (const float4*)atom_rep;  // [t][AB][32 float4]
    size_t repT = (size_t)AB * 32;
#pragma unroll 4
    for (int k = 0; k < 32; k++) {
        int el = base + k;
        int dst = s_dst[el];
        if (dst < 0) continue;  // warp-uniform (only in last block)
        float c0 = s_sc[el * 4 + 0];
        float c1 = s_sc[el * 4 + 1];
        float c2 = s_sc[el * 4 + 2];
        int src = s_src[el];
        const float4* p0 = rep4 + (size_t)src * 32 + lane;
        float4 a0 = __ldg(p0);
        float4 a1 = __ldg(p0 + repT);
        float4 a2 = __ldg(p0 + 2 * repT);
        float4 m;
        m.x = fmaf(c0, a0.x, fmaf(c1, a1.x, c2 * a2.x));
        m.y = fmaf(c0, a0.y, fmaf(c1, a1.y, c2 * a2.y));
        m.z = fmaf(c0, a0.z, fmaf(c1, a1.z, c2 * a2.z));
        m.w = fmaf(c0, a0.w, fmaf(c1, a1.w, c2 * a2.w));
        float* dptr = probes + (size_t)dst * 128 + lane * 4;
        asm volatile("red.global.add.v4.f32 [%0], {%1, %2, %3, %4};"
                     :: "l"(dptr), "f"(m.x), "f"(m.y), "f"(m.z), "f"(m.w)
                     : "memory");
        if (lane == 0) {
            float ov = fmaf(c0, rw_table[src],
                       fmaf(c1, rw_table[AB + src],
                            c2 * rw_table[2 * AB + src]));
            atomicAdd(out + dst, ov);
        }
    }
}

extern "C" void kernel_launch(void* const* d_in, const int* in_sizes, int n_in,
                              void* d_out, int out_size)
{
    const float* atom_xyz  = (const float*)d_in[0];
    const float* probe_xyz = (const float*)d_in[1];
    const int*   edges     = (const int*)d_in[2];
    const float* ped       = (const float*)d_in[3];
    const float* cell      = (const float*)d_in[4];
    const float* atom_rep  = (const float*)d_in[8];
    const float* w1        = (const float*)d_in[9];
    const float* w2        = (const float*)d_in[10];
    const float* w_out     = (const float*)d_in[11];

    int B         = in_sizes[4] / 9;
    int n_atoms   = in_sizes[0] / (3 * B);
    int n_probes  = in_sizes[1] / (3 * B);
    int n_edges_b = in_sizes[2] / (2 * B);
    int E  = B * n_edges_b;
    int AB = B * n_atoms;
    int P  = B * n_probes;

    float* out    = (float*)d_out;      // first P elements: (B,P) potential
    float* probes = out + P;            // next P*128: probe features

    // zero out + probes in one shot (contiguous)
    cudaMemsetAsync(d_out, 0, (size_t)(P + (size_t)P * 128) * sizeof(float), 0);
    build_table_kernel<<<(TN + 7) / 8, 256>>>(w1, w2);
    rw_kernel<<<(3 * AB * 32 + 255) / 256, 256>>>(atom_rep, w_out, 3 * AB);
    edge_kernel<<<(E + 255) / 256, 256>>>(atom_xyz, probe_xyz, edges, ped, cell,
                                          atom_rep, probes, out,
                                          E, n_edges_b, n_atoms, n_probes, AB);
}